// round 8
// baseline (speedup 1.0000x reference)
#include <cuda_runtime.h>
#include <cuda_bf16.h>
#include <math.h>

// ---------------------------------------------------------------------------
// Problem constants
// ---------------------------------------------------------------------------
#define BATCH   2
#define S_LEN   2048
#define HDIM    2048
#define HK      16
#define HV      32
#define DK      128
#define DV      128
#define KCONV   4
#define KEY_DIM   (HK*DK)            // 2048
#define VAL_DIM   (HV*DV)            // 4096
#define QKVZ_COLS (2*KEY_DIM + 2*VAL_DIM)  // 12288
#define NTOK    (BATCH*S_LEN)        // 4096
#define EPSV    1e-6f

// ---------------------------------------------------------------------------
// Scratch (static device globals; allocated at module load — no runtime alloc)
// ---------------------------------------------------------------------------
__device__ float g_qkvz [ (size_t)NTOK * QKVZ_COLS ];   // 201 MB
__device__ float g_ba   [ (size_t)NTOK * 64 ];
__device__ float g_q    [ (size_t)NTOK * KEY_DIM ];
__device__ float g_k    [ (size_t)NTOK * KEY_DIM ];
__device__ float g_v    [ (size_t)NTOK * VAL_DIM ];
__device__ float g_decay[ (size_t)NTOK * HV ];
__device__ float g_beta [ (size_t)NTOK * HV ];
__device__ float g_core [ (size_t)NTOK * VAL_DIM ];
__device__ float g_y    [ (size_t)NTOK * VAL_DIM ];

// ---------------------------------------------------------------------------
// Packed f32x2 helpers (Blackwell sm_103a)
// ---------------------------------------------------------------------------
__device__ __forceinline__ float2 ffma2(float2 a, float2 b, float2 c) {
    float2 d;
    asm("fma.rn.f32x2 %0, %1, %2, %3;"
        : "=l"(reinterpret_cast<unsigned long long&>(d))
        : "l"(reinterpret_cast<unsigned long long&>(a)),
          "l"(reinterpret_cast<unsigned long long&>(b)),
          "l"(reinterpret_cast<unsigned long long&>(c)));
    return d;
}
__device__ __forceinline__ float2 fmul2(float2 a, float2 b) {
    float2 d;
    asm("mul.rn.f32x2 %0, %1, %2;"
        : "=l"(reinterpret_cast<unsigned long long&>(d))
        : "l"(reinterpret_cast<unsigned long long&>(a)),
          "l"(reinterpret_cast<unsigned long long&>(b)));
    return d;
}

// ---------------------------------------------------------------------------
// SGEMM: C[M,N] = A[M,K] @ B[K,N], fp32, row-major.
// 128x128 block tile, BK=16, 256 threads, 8x8 per thread, f32x2 microkernel.
// M % 128 == 0, K % 16 == 0 assumed (true for all call sites).
// N guarded (needed for N=64 w_ba GEMM).
// ---------------------------------------------------------------------------
__global__ __launch_bounds__(256, 2)
void sgemm_kernel(const float* __restrict__ A, const float* __restrict__ B,
                  float* __restrict__ C, int M, int N, int K)
{
    __shared__ __align__(16) float As[16][128];
    __shared__ __align__(16) float Bs[16][128];

    const int tid = threadIdx.x;
    const int tx  = tid & 15;   // N direction
    const int ty  = tid >> 4;   // M direction
    const int m0  = blockIdx.y * 128;
    const int n0  = blockIdx.x * 128;

    float2 cc[8][4];
#pragma unroll
    for (int i = 0; i < 8; i++)
#pragma unroll
        for (int j = 0; j < 4; j++) cc[i][j] = make_float2(0.f, 0.f);

    for (int k0 = 0; k0 < K; k0 += 16) {
        // --- load A tile (128 x 16), store transposed As[k][m] ---
#pragma unroll
        for (int q = 0; q < 2; q++) {
            int item = q * 256 + tid;             // 0..511 float4 items
            int ar = item >> 2;                   // 0..127
            int ac = (item & 3) * 4;              // 0,4,8,12
            float4 va = *reinterpret_cast<const float4*>(
                &A[(size_t)(m0 + ar) * K + k0 + ac]);
            As[ac + 0][ar] = va.x;
            As[ac + 1][ar] = va.y;
            As[ac + 2][ar] = va.z;
            As[ac + 3][ar] = va.w;
        }
        // --- load B tile (16 x 128) ---
#pragma unroll
        for (int q = 0; q < 2; q++) {
            int item = q * 256 + tid;
            int br = item >> 5;                   // 0..15
            int bc = (item & 31) * 4;             // 0..124
            float4 vb = make_float4(0.f, 0.f, 0.f, 0.f);
            if (n0 + bc < N)
                vb = *reinterpret_cast<const float4*>(
                    &B[(size_t)(k0 + br) * N + n0 + bc]);
            *reinterpret_cast<float4*>(&Bs[br][bc]) = vb;
        }
        __syncthreads();

#pragma unroll
        for (int kk = 0; kk < 16; kk++) {
            float4 a0 = *reinterpret_cast<const float4*>(&As[kk][ty * 8]);
            float4 a1 = *reinterpret_cast<const float4*>(&As[kk][ty * 8 + 4]);
            float4 b0 = *reinterpret_cast<const float4*>(&Bs[kk][tx * 8]);
            float4 b1 = *reinterpret_cast<const float4*>(&Bs[kk][tx * 8 + 4]);
            float  aa[8] = {a0.x, a0.y, a0.z, a0.w, a1.x, a1.y, a1.z, a1.w};
            float2 bb[4] = { make_float2(b0.x, b0.y), make_float2(b0.z, b0.w),
                             make_float2(b1.x, b1.y), make_float2(b1.z, b1.w) };
#pragma unroll
            for (int i = 0; i < 8; i++) {
                float2 a2 = make_float2(aa[i], aa[i]);
#pragma unroll
                for (int j = 0; j < 4; j++)
                    cc[i][j] = ffma2(a2, bb[j], cc[i][j]);
            }
        }
        __syncthreads();
    }

    // --- epilogue ---
#pragma unroll
    for (int i = 0; i < 8; i++) {
        size_t row = (size_t)(m0 + ty * 8 + i) * N;
        int col = n0 + tx * 8;
        if (col < N) {
            float4 o0 = make_float4(cc[i][0].x, cc[i][0].y, cc[i][1].x, cc[i][1].y);
            *reinterpret_cast<float4*>(&C[row + col]) = o0;
        }
        if (col + 4 < N) {
            float4 o1 = make_float4(cc[i][2].x, cc[i][2].y, cc[i][3].x, cc[i][3].y);
            *reinterpret_cast<float4*>(&C[row + col + 4]) = o1;
        }
    }
}

// ---------------------------------------------------------------------------
// Conv(K=4, causal) + silu + l2norm(q,k) ; also g->decay, beta gates.
// One block per token; 512 threads = 16 warps; warp handles 4 of 64
// channel-groups (each group = 128 channels = one head's q/k/v slice).
// ---------------------------------------------------------------------------
__global__ __launch_bounds__(512)
void conv_kernel(const float* __restrict__ qkvz, const float* __restrict__ ba,
                 const float* __restrict__ conv_w, const float* __restrict__ A_log,
                 const float* __restrict__ dt_bias,
                 float* __restrict__ qo, float* __restrict__ ko,
                 float* __restrict__ vo, float* __restrict__ decay,
                 float* __restrict__ beta)
{
    const int bs   = blockIdx.x;           // b*S + s
    const int s    = bs & (S_LEN - 1);
    const int tid  = threadIdx.x;
    const int warp = tid >> 5;
    const int lane = tid & 31;

    // gates (32 heads)
    if (tid < 32) {
        int hv = tid;
        float bg = ba[(size_t)bs * 64 + (hv >> 1) * 4 + (hv & 1)];
        float ag = ba[(size_t)bs * 64 + (hv >> 1) * 4 + 2 + (hv & 1)];
        float x  = ag + dt_bias[hv];
        float sp = (x > 20.f) ? x : log1pf(expf(x));
        float gg = -expf(A_log[hv]) * sp;
        decay[(size_t)bs * HV + hv] = expf(gg);
        beta [(size_t)bs * HV + hv] = 1.f / (1.f + expf(-bg));
    }

    for (int g = warp; g < 64; g += 16) {
        float vals[4];
        float sumsq = 0.f;
#pragma unroll
        for (int i = 0; i < 4; i++) {
            int d = lane + 32 * i;
            int c = g * 128 + d;                 // mixed-channel index
            int col;
            if (g < 16)       col = g * 768 + d;                               // q
            else if (g < 32)  col = (g - 16) * 768 + 128 + d;                  // k
            else              col = ((g - 32) >> 1) * 768 + 256
                                    + ((g - 32) & 1) * 128 + d;                // v
            float4 w4 = *reinterpret_cast<const float4*>(&conv_w[(size_t)c * 4]);
            float wj[4] = {w4.x, w4.y, w4.z, w4.w};
            float acc = 0.f;
#pragma unroll
            for (int j = 0; j < 4; j++) {
                int sj = s - 3 + j;
                if (sj >= 0)
                    acc += qkvz[(size_t)(bs - 3 + j) * QKVZ_COLS + col] * wj[j];
            }
            float sv = acc / (1.f + expf(-acc));   // silu
            vals[i] = sv;
            sumsq += sv * sv;
        }
        if (g < 32) {   // q or k: l2norm over 128 dims (warp owns whole group)
#pragma unroll
            for (int off = 16; off; off >>= 1)
                sumsq += __shfl_xor_sync(0xffffffffu, sumsq, off);
            float rn = rsqrtf(sumsq + EPSV);
            float* dst = (g < 16)
                ? &qo[((size_t)bs * HK + g) * DK]
                : &ko[((size_t)bs * HK + (g - 16)) * DK];
#pragma unroll
            for (int i = 0; i < 4; i++) dst[lane + 32 * i] = vals[i] * rn;
        } else {
            float* dst = &vo[((size_t)bs * HV + (g - 32)) * DV];
#pragma unroll
            for (int i = 0; i < 4; i++) dst[lane + 32 * i] = vals[i];
        }
    }
}

// ---------------------------------------------------------------------------
// Gated delta-rule scan. Grid = B*HV*2 = 128 blocks (DV split in halves).
// 256 threads: p = tid>>6 owns k-rows [32p,32p+32), vl = tid&63 owns one
// v-column of this block's half. State (32 x 1) per thread in 16 f32x2 regs.
// Per step: S *= exp(g); kv = k^T S; S += k (beta (v - kv))^T; o = scale q^T S
// ---------------------------------------------------------------------------
__global__ __launch_bounds__(256)
void scan_kernel(const float* __restrict__ qo, const float* __restrict__ ko,
                 const float* __restrict__ vo, const float* __restrict__ decay,
                 const float* __restrict__ beta, float* __restrict__ core)
{
    const int blk = blockIdx.x;
    const int b   = blk >> 6;
    const int h   = (blk >> 1) & 31;
    const int vh  = blk & 1;
    const int hq  = h >> 1;
    const int tid = threadIdx.x;
    const int p   = tid >> 6;
    const int vl  = tid & 63;

    __shared__ __align__(16) float sh_q[128];
    __shared__ __align__(16) float sh_k[128];
    __shared__ __align__(16) float sh_v[64];
    __shared__ float red_kv[256];
    __shared__ float red_o[256];
    __shared__ float sh_scal[2];

    const float scale = 0.088388347648318447f;   // DK^-0.5

    float2 Sst[16];
#pragma unroll
    for (int j = 0; j < 16; j++) Sst[j] = make_float2(0.f, 0.f);

    const float* qp = qo + ((size_t)b * S_LEN * HK + hq) * DK;
    const float* kp = ko + ((size_t)b * S_LEN * HK + hq) * DK;
    const float* vp = vo + ((size_t)b * S_LEN * HV + h) * DV + vh * 64;
    const float* dp = decay + (size_t)b * S_LEN * HV + h;
    const float* bp = beta  + (size_t)b * S_LEN * HV + h;
    float* op = core + ((size_t)b * S_LEN * HV + h) * DV + vh * 64;

    // prefetch t = 0
    float pq = 0.f, pk = 0.f, pv = 0.f, pd = 0.f, pb = 0.f;
    if (tid < 128) { pq = qp[tid]; pk = kp[tid]; }
    if (tid < 64)  { pv = vp[tid]; }
    if (tid == 0)  { pd = dp[0]; pb = bp[0]; }

    for (int t = 0; t < S_LEN; ++t) {
        __syncthreads();                       // step t-1 fully done
        if (t > 0 && p == 0) {                 // flush o(t-1)
            float o = red_o[vl] + red_o[64 + vl] + red_o[128 + vl] + red_o[192 + vl];
            op[(size_t)(t - 1) * VAL_DIM + vl] = o * scale;
        }
        if (tid < 128) { sh_q[tid] = pq; sh_k[tid] = pk; }
        if (tid < 64)  { sh_v[tid] = pv; }
        if (tid == 0)  { sh_scal[0] = pd; sh_scal[1] = pb; }
        if (t + 1 < S_LEN) {                   // prefetch t+1 under compute
            if (tid < 128) {
                pq = qp[(size_t)(t + 1) * KEY_DIM + tid];
                pk = kp[(size_t)(t + 1) * KEY_DIM + tid];
            }
            if (tid < 64)  pv = vp[(size_t)(t + 1) * VAL_DIM + tid];
            if (tid == 0)  { pd = dp[(size_t)(t + 1) * HV]; pb = bp[(size_t)(t + 1) * HV]; }
        }
        __syncthreads();                       // shared tile ready

        const float2* k2 = reinterpret_cast<const float2*>(sh_k + p * 32);
        float2 acc = make_float2(0.f, 0.f);
#pragma unroll
        for (int j = 0; j < 16; j++) acc = ffma2(k2[j], Sst[j], acc);
        red_kv[p * 64 + vl] = acc.x + acc.y;
        __syncthreads();                       // kv partials ready

        float dec = sh_scal[0];
        float bet = sh_scal[1];
        float kv = dec * (red_kv[vl] + red_kv[64 + vl] + red_kv[128 + vl] + red_kv[192 + vl]);
        float u  = bet * (sh_v[vl] - kv);
        float2 u2 = make_float2(u, u);
        float2 d2 = make_float2(dec, dec);
        const float2* q2 = reinterpret_cast<const float2*>(sh_q + p * 32);
        float2 oacc = make_float2(0.f, 0.f);
#pragma unroll
        for (int j = 0; j < 16; j++) {
            Sst[j] = ffma2(Sst[j], d2, fmul2(k2[j], u2));
            oacc   = ffma2(q2[j], Sst[j], oacc);
        }
        red_o[p * 64 + vl] = oacc.x + oacc.y;
        // no trailing sync: next iter's first sync covers red_o visibility
    }
    __syncthreads();
    if (p == 0) {
        float o = red_o[vl] + red_o[64 + vl] + red_o[128 + vl] + red_o[192 + vl];
        op[(size_t)(S_LEN - 1) * VAL_DIM + vl] = o * scale;
    }
}

// ---------------------------------------------------------------------------
// Gated RMSNorm: y = core * rsqrt(mean(core^2)+eps) * norm_w * silu(z)
// Block per token, 32 warps = 32 heads, 4 values per lane.
// ---------------------------------------------------------------------------
__global__ __launch_bounds__(1024)
void post_kernel(const float* __restrict__ core, const float* __restrict__ qkvz,
                 const float* __restrict__ norm_w, float* __restrict__ y)
{
    const int bs   = blockIdx.x;
    const int warp = threadIdx.x >> 5;   // head hv
    const int lane = threadIdx.x & 31;

    const float* cp = core + ((size_t)bs * HV + warp) * DV;
    const int zcol  = (warp >> 1) * 768 + 512 + (warp & 1) * 128;
    const float* zp = qkvz + (size_t)bs * QKVZ_COLS + zcol;

    float c[4];
    float ss = 0.f;
#pragma unroll
    for (int i = 0; i < 4; i++) {
        c[i] = cp[lane + 32 * i];
        ss += c[i] * c[i];
    }
#pragma unroll
    for (int off = 16; off; off >>= 1) ss += __shfl_xor_sync(0xffffffffu, ss, off);
    float rn = rsqrtf(ss * (1.f / 128.f) + EPSV);

    float* yp = y + (size_t)bs * VAL_DIM + warp * DV;
#pragma unroll
    for (int i = 0; i < 4; i++) {
        int d = lane + 32 * i;
        float z  = zp[d];
        float sz = z / (1.f + expf(-z));
        yp[d] = c[i] * rn * norm_w[d] * sz;
    }
}

// ---------------------------------------------------------------------------
// Launch
// ---------------------------------------------------------------------------
extern "C" void kernel_launch(void* const* d_in, const int* in_sizes, int n_in,
                              void* d_out, int out_size)
{
    const float* hs     = (const float*)d_in[0];
    const float* w_qkvz = (const float*)d_in[1];
    const float* w_ba   = (const float*)d_in[2];
    const float* conv_w = (const float*)d_in[3];
    const float* A_log  = (const float*)d_in[4];
    const float* dt_b   = (const float*)d_in[5];
    const float* norm_w = (const float*)d_in[6];
    const float* w_out  = (const float*)d_in[7];
    float* out = (float*)d_out;

    void *p_qkvz, *p_ba, *p_q, *p_k, *p_v, *p_dec, *p_bet, *p_core, *p_y;
    cudaGetSymbolAddress(&p_qkvz, g_qkvz);
    cudaGetSymbolAddress(&p_ba,   g_ba);
    cudaGetSymbolAddress(&p_q,    g_q);
    cudaGetSymbolAddress(&p_k,    g_k);
    cudaGetSymbolAddress(&p_v,    g_v);
    cudaGetSymbolAddress(&p_dec,  g_decay);
    cudaGetSymbolAddress(&p_bet,  g_beta);
    cudaGetSymbolAddress(&p_core, g_core);
    cudaGetSymbolAddress(&p_y,    g_y);

    float* qkvz = (float*)p_qkvz;
    float* ba   = (float*)p_ba;
    float* q    = (float*)p_q;
    float* k    = (float*)p_k;
    float* v    = (float*)p_v;
    float* dec  = (float*)p_dec;
    float* bet  = (float*)p_bet;
    float* core = (float*)p_core;
    float* y    = (float*)p_y;

    // 1) qkvz = hs @ w_qkvz   (4096 x 12288 x 2048)
    sgemm_kernel<<<dim3(QKVZ_COLS / 128, NTOK / 128), 256>>>(
        hs, w_qkvz, qkvz, NTOK, QKVZ_COLS, HDIM);

    // 2) ba = hs @ w_ba       (4096 x 64 x 2048)
    sgemm_kernel<<<dim3(1, NTOK / 128), 256>>>(hs, w_ba, ba, NTOK, 64, HDIM);

    // 3) conv + silu + l2norm + gates
    conv_kernel<<<NTOK, 512>>>(qkvz, ba, conv_w, A_log, dt_b,
                               q, k, v, dec, bet);

    // 4) delta-rule scan
    scan_kernel<<<BATCH * HV * 2, 256>>>(q, k, v, dec, bet, core);

    // 5) gated RMSNorm
    post_kernel<<<NTOK, 1024>>>(core, qkvz, norm_w, y);

    // 6) out = y @ w_out      (4096 x 2048 x 4096)
    sgemm_kernel<<<dim3(HDIM / 128, NTOK / 128), 256>>>(
        y, w_out, out, NTOK, HDIM, VAL_DIM);
}

// round 9
// speedup vs baseline: 1.0001x; 1.0001x over previous
#include <cuda_runtime.h>
#include <cuda_bf16.h>
#include <math.h>

// ---------------------------------------------------------------------------
// Problem constants
// ---------------------------------------------------------------------------
#define BATCH   2
#define S_LEN   2048
#define HDIM    2048
#define HK      16
#define HV      32
#define DK      128
#define DV      128
#define KCONV   4
#define KEY_DIM   (HK*DK)            // 2048
#define VAL_DIM   (HV*DV)            // 4096
#define QKVZ_COLS (2*KEY_DIM + 2*VAL_DIM)  // 12288
#define NTOK    (BATCH*S_LEN)        // 4096
#define EPSV    1e-6f

// ---------------------------------------------------------------------------
// Scratch (static device globals; allocated at module load — no runtime alloc)
// ---------------------------------------------------------------------------
__device__ float g_qkvz [ (size_t)NTOK * QKVZ_COLS ];   // 201 MB
__device__ float g_ba   [ (size_t)NTOK * 64 ];
__device__ float g_q    [ (size_t)NTOK * KEY_DIM ];
__device__ float g_k    [ (size_t)NTOK * KEY_DIM ];
__device__ float g_v    [ (size_t)NTOK * VAL_DIM ];
__device__ float g_decay[ (size_t)NTOK * HV ];
__device__ float g_beta [ (size_t)NTOK * HV ];
__device__ float g_core [ (size_t)NTOK * VAL_DIM ];
__device__ float g_y    [ (size_t)NTOK * VAL_DIM ];

// ---------------------------------------------------------------------------
// Packed f32x2 helpers (Blackwell sm_103a)
// ---------------------------------------------------------------------------
__device__ __forceinline__ float2 ffma2(float2 a, float2 b, float2 c) {
    float2 d;
    asm("fma.rn.f32x2 %0, %1, %2, %3;"
        : "=l"(reinterpret_cast<unsigned long long&>(d))
        : "l"(reinterpret_cast<unsigned long long&>(a)),
          "l"(reinterpret_cast<unsigned long long&>(b)),
          "l"(reinterpret_cast<unsigned long long&>(c)));
    return d;
}
__device__ __forceinline__ float2 fmul2(float2 a, float2 b) {
    float2 d;
    asm("mul.rn.f32x2 %0, %1, %2;"
        : "=l"(reinterpret_cast<unsigned long long&>(d))
        : "l"(reinterpret_cast<unsigned long long&>(a)),
          "l"(reinterpret_cast<unsigned long long&>(b)));
    return d;
}

// ---------------------------------------------------------------------------
// SGEMM: C[M,N] = A[M,K] @ B[K,N], fp32, row-major.
// 128x128 block tile, BK=16, 256 threads, 8x8 per thread, f32x2 microkernel.
// M % 128 == 0, K % 16 == 0 assumed (true for all call sites).
// N guarded (needed for N=64 w_ba GEMM).
// ---------------------------------------------------------------------------
__global__ __launch_bounds__(256, 2)
void sgemm_kernel(const float* __restrict__ A, const float* __restrict__ B,
                  float* __restrict__ C, int M, int N, int K)
{
    __shared__ __align__(16) float As[16][128];
    __shared__ __align__(16) float Bs[16][128];

    const int tid = threadIdx.x;
    const int tx  = tid & 15;   // N direction
    const int ty  = tid >> 4;   // M direction
    const int m0  = blockIdx.y * 128;
    const int n0  = blockIdx.x * 128;

    float2 cc[8][4];
#pragma unroll
    for (int i = 0; i < 8; i++)
#pragma unroll
        for (int j = 0; j < 4; j++) cc[i][j] = make_float2(0.f, 0.f);

    for (int k0 = 0; k0 < K; k0 += 16) {
        // --- load A tile (128 x 16), store transposed As[k][m] ---
#pragma unroll
        for (int q = 0; q < 2; q++) {
            int item = q * 256 + tid;             // 0..511 float4 items
            int ar = item >> 2;                   // 0..127
            int ac = (item & 3) * 4;              // 0,4,8,12
            float4 va = *reinterpret_cast<const float4*>(
                &A[(size_t)(m0 + ar) * K + k0 + ac]);
            As[ac + 0][ar] = va.x;
            As[ac + 1][ar] = va.y;
            As[ac + 2][ar] = va.z;
            As[ac + 3][ar] = va.w;
        }
        // --- load B tile (16 x 128) ---
#pragma unroll
        for (int q = 0; q < 2; q++) {
            int item = q * 256 + tid;
            int br = item >> 5;                   // 0..15
            int bc = (item & 31) * 4;             // 0..124
            float4 vb = make_float4(0.f, 0.f, 0.f, 0.f);
            if (n0 + bc < N)
                vb = *reinterpret_cast<const float4*>(
                    &B[(size_t)(k0 + br) * N + n0 + bc]);
            *reinterpret_cast<float4*>(&Bs[br][bc]) = vb;
        }
        __syncthreads();

#pragma unroll
        for (int kk = 0; kk < 16; kk++) {
            float4 a0 = *reinterpret_cast<const float4*>(&As[kk][ty * 8]);
            float4 a1 = *reinterpret_cast<const float4*>(&As[kk][ty * 8 + 4]);
            float4 b0 = *reinterpret_cast<const float4*>(&Bs[kk][tx * 8]);
            float4 b1 = *reinterpret_cast<const float4*>(&Bs[kk][tx * 8 + 4]);
            float  aa[8] = {a0.x, a0.y, a0.z, a0.w, a1.x, a1.y, a1.z, a1.w};
            float2 bb[4] = { make_float2(b0.x, b0.y), make_float2(b0.z, b0.w),
                             make_float2(b1.x, b1.y), make_float2(b1.z, b1.w) };
#pragma unroll
            for (int i = 0; i < 8; i++) {
                float2 a2 = make_float2(aa[i], aa[i]);
#pragma unroll
                for (int j = 0; j < 4; j++)
                    cc[i][j] = ffma2(a2, bb[j], cc[i][j]);
            }
        }
        __syncthreads();
    }

    // --- epilogue ---
#pragma unroll
    for (int i = 0; i < 8; i++) {
        size_t row = (size_t)(m0 + ty * 8 + i) * N;
        int col = n0 + tx * 8;
        if (col < N) {
            float4 o0 = make_float4(cc[i][0].x, cc[i][0].y, cc[i][1].x, cc[i][1].y);
            *reinterpret_cast<float4*>(&C[row + col]) = o0;
        }
        if (col + 4 < N) {
            float4 o1 = make_float4(cc[i][2].x, cc[i][2].y, cc[i][3].x, cc[i][3].y);
            *reinterpret_cast<float4*>(&C[row + col + 4]) = o1;
        }
    }
}

// ---------------------------------------------------------------------------
// Conv(K=4, causal) + silu + l2norm(q,k) ; also g->decay, beta gates.
// One block per token; 512 threads = 16 warps; warp handles 4 of 64
// channel-groups (each group = 128 channels = one head's q/k/v slice).
// ---------------------------------------------------------------------------
__global__ __launch_bounds__(512)
void conv_kernel(const float* __restrict__ qkvz, const float* __restrict__ ba,
                 const float* __restrict__ conv_w, const float* __restrict__ A_log,
                 const float* __restrict__ dt_bias,
                 float* __restrict__ qo, float* __restrict__ ko,
                 float* __restrict__ vo, float* __restrict__ decay,
                 float* __restrict__ beta)
{
    const int bs   = blockIdx.x;           // b*S + s
    const int s    = bs & (S_LEN - 1);
    const int tid  = threadIdx.x;
    const int warp = tid >> 5;
    const int lane = tid & 31;

    // gates (32 heads)
    if (tid < 32) {
        int hv = tid;
        float bg = ba[(size_t)bs * 64 + (hv >> 1) * 4 + (hv & 1)];
        float ag = ba[(size_t)bs * 64 + (hv >> 1) * 4 + 2 + (hv & 1)];
        float x  = ag + dt_bias[hv];
        float sp = (x > 20.f) ? x : log1pf(expf(x));
        float gg = -expf(A_log[hv]) * sp;
        decay[(size_t)bs * HV + hv] = expf(gg);
        beta [(size_t)bs * HV + hv] = 1.f / (1.f + expf(-bg));
    }

    for (int g = warp; g < 64; g += 16) {
        float vals[4];
        float sumsq = 0.f;
#pragma unroll
        for (int i = 0; i < 4; i++) {
            int d = lane + 32 * i;
            int c = g * 128 + d;                 // mixed-channel index
            int col;
            if (g < 16)       col = g * 768 + d;                               // q
            else if (g < 32)  col = (g - 16) * 768 + 128 + d;                  // k
            else              col = ((g - 32) >> 1) * 768 + 256
                                    + ((g - 32) & 1) * 128 + d;                // v
            float4 w4 = *reinterpret_cast<const float4*>(&conv_w[(size_t)c * 4]);
            float wj[4] = {w4.x, w4.y, w4.z, w4.w};
            float acc = 0.f;
#pragma unroll
            for (int j = 0; j < 4; j++) {
                int sj = s - 3 + j;
                if (sj >= 0)
                    acc += qkvz[(size_t)(bs - 3 + j) * QKVZ_COLS + col] * wj[j];
            }
            float sv = acc / (1.f + expf(-acc));   // silu
            vals[i] = sv;
            sumsq += sv * sv;
        }
        if (g < 32) {   // q or k: l2norm over 128 dims (warp owns whole group)
#pragma unroll
            for (int off = 16; off; off >>= 1)
                sumsq += __shfl_xor_sync(0xffffffffu, sumsq, off);
            float rn = rsqrtf(sumsq + EPSV);
            float* dst = (g < 16)
                ? &qo[((size_t)bs * HK + g) * DK]
                : &ko[((size_t)bs * HK + (g - 16)) * DK];
#pragma unroll
            for (int i = 0; i < 4; i++) dst[lane + 32 * i] = vals[i] * rn;
        } else {
            float* dst = &vo[((size_t)bs * HV + (g - 32)) * DV];
#pragma unroll
            for (int i = 0; i < 4; i++) dst[lane + 32 * i] = vals[i];
        }
    }
}

// ---------------------------------------------------------------------------
// Gated delta-rule scan. Grid = B*HV*2 = 128 blocks (DV split in halves).
// 256 threads: p = tid>>6 owns k-rows [32p,32p+32), vl = tid&63 owns one
// v-column of this block's half. State (32 x 1) per thread in 16 f32x2 regs.
// Per step: S *= exp(g); kv = k^T S; S += k (beta (v - kv))^T; o = scale q^T S
// ---------------------------------------------------------------------------
__global__ __launch_bounds__(256)
void scan_kernel(const float* __restrict__ qo, const float* __restrict__ ko,
                 const float* __restrict__ vo, const float* __restrict__ decay,
                 const float* __restrict__ beta, float* __restrict__ core)
{
    const int blk = blockIdx.x;
    const int b   = blk >> 6;
    const int h   = (blk >> 1) & 31;
    const int vh  = blk & 1;
    const int hq  = h >> 1;
    const int tid = threadIdx.x;
    const int p   = tid >> 6;
    const int vl  = tid & 63;

    __shared__ __align__(16) float sh_q[128];
    __shared__ __align__(16) float sh_k[128];
    __shared__ __align__(16) float sh_v[64];
    __shared__ float red_kv[256];
    __shared__ float red_o[256];
    __shared__ float sh_scal[2];

    const float scale = 0.088388347648318447f;   // DK^-0.5

    float2 Sst[16];
#pragma unroll
    for (int j = 0; j < 16; j++) Sst[j] = make_float2(0.f, 0.f);

    const float* qp = qo + ((size_t)b * S_LEN * HK + hq) * DK;
    const float* kp = ko + ((size_t)b * S_LEN * HK + hq) * DK;
    const float* vp = vo + ((size_t)b * S_LEN * HV + h) * DV + vh * 64;
    const float* dp = decay + (size_t)b * S_LEN * HV + h;
    const float* bp = beta  + (size_t)b * S_LEN * HV + h;
    float* op = core + ((size_t)b * S_LEN * HV + h) * DV + vh * 64;

    // prefetch t = 0
    float pq = 0.f, pk = 0.f, pv = 0.f, pd = 0.f, pb = 0.f;
    if (tid < 128) { pq = qp[tid]; pk = kp[tid]; }
    if (tid < 64)  { pv = vp[tid]; }
    if (tid == 0)  { pd = dp[0]; pb = bp[0]; }

    for (int t = 0; t < S_LEN; ++t) {
        __syncthreads();                       // step t-1 fully done
        if (t > 0 && p == 0) {                 // flush o(t-1)
            float o = red_o[vl] + red_o[64 + vl] + red_o[128 + vl] + red_o[192 + vl];
            op[(size_t)(t - 1) * VAL_DIM + vl] = o * scale;
        }
        if (tid < 128) { sh_q[tid] = pq; sh_k[tid] = pk; }
        if (tid < 64)  { sh_v[tid] = pv; }
        if (tid == 0)  { sh_scal[0] = pd; sh_scal[1] = pb; }
        if (t + 1 < S_LEN) {                   // prefetch t+1 under compute
            if (tid < 128) {
                pq = qp[(size_t)(t + 1) * KEY_DIM + tid];
                pk = kp[(size_t)(t + 1) * KEY_DIM + tid];
            }
            if (tid < 64)  pv = vp[(size_t)(t + 1) * VAL_DIM + tid];
            if (tid == 0)  { pd = dp[(size_t)(t + 1) * HV]; pb = bp[(size_t)(t + 1) * HV]; }
        }
        __syncthreads();                       // shared tile ready

        const float2* k2 = reinterpret_cast<const float2*>(sh_k + p * 32);
        float2 acc = make_float2(0.f, 0.f);
#pragma unroll
        for (int j = 0; j < 16; j++) acc = ffma2(k2[j], Sst[j], acc);
        red_kv[p * 64 + vl] = acc.x + acc.y;
        __syncthreads();                       // kv partials ready

        float dec = sh_scal[0];
        float bet = sh_scal[1];
        float kv = dec * (red_kv[vl] + red_kv[64 + vl] + red_kv[128 + vl] + red_kv[192 + vl]);
        float u  = bet * (sh_v[vl] - kv);
        float2 u2 = make_float2(u, u);
        float2 d2 = make_float2(dec, dec);
        const float2* q2 = reinterpret_cast<const float2*>(sh_q + p * 32);
        float2 oacc = make_float2(0.f, 0.f);
#pragma unroll
        for (int j = 0; j < 16; j++) {
            Sst[j] = ffma2(Sst[j], d2, fmul2(k2[j], u2));
            oacc   = ffma2(q2[j], Sst[j], oacc);
        }
        red_o[p * 64 + vl] = oacc.x + oacc.y;
        // no trailing sync: next iter's first sync covers red_o visibility
    }
    __syncthreads();
    if (p == 0) {
        float o = red_o[vl] + red_o[64 + vl] + red_o[128 + vl] + red_o[192 + vl];
        op[(size_t)(S_LEN - 1) * VAL_DIM + vl] = o * scale;
    }
}

// ---------------------------------------------------------------------------
// Gated RMSNorm: y = core * rsqrt(mean(core^2)+eps) * norm_w * silu(z)
// Block per token, 32 warps = 32 heads, 4 values per lane.
// ---------------------------------------------------------------------------
__global__ __launch_bounds__(1024)
void post_kernel(const float* __restrict__ core, const float* __restrict__ qkvz,
                 const float* __restrict__ norm_w, float* __restrict__ y)
{
    const int bs   = blockIdx.x;
    const int warp = threadIdx.x >> 5;   // head hv
    const int lane = threadIdx.x & 31;

    const float* cp = core + ((size_t)bs * HV + warp) * DV;
    const int zcol  = (warp >> 1) * 768 + 512 + (warp & 1) * 128;
    const float* zp = qkvz + (size_t)bs * QKVZ_COLS + zcol;

    float c[4];
    float ss = 0.f;
#pragma unroll
    for (int i = 0; i < 4; i++) {
        c[i] = cp[lane + 32 * i];
        ss += c[i] * c[i];
    }
#pragma unroll
    for (int off = 16; off; off >>= 1) ss += __shfl_xor_sync(0xffffffffu, ss, off);
    float rn = rsqrtf(ss * (1.f / 128.f) + EPSV);

    float* yp = y + (size_t)bs * VAL_DIM + warp * DV;
#pragma unroll
    for (int i = 0; i < 4; i++) {
        int d = lane + 32 * i;
        float z  = zp[d];
        float sz = z / (1.f + expf(-z));
        yp[d] = c[i] * rn * norm_w[d] * sz;
    }
}

// ---------------------------------------------------------------------------
// Launch
// ---------------------------------------------------------------------------
extern "C" void kernel_launch(void* const* d_in, const int* in_sizes, int n_in,
                              void* d_out, int out_size)
{
    const float* hs     = (const float*)d_in[0];
    const float* w_qkvz = (const float*)d_in[1];
    const float* w_ba   = (const float*)d_in[2];
    const float* conv_w = (const float*)d_in[3];
    const float* A_log  = (const float*)d_in[4];
    const float* dt_b   = (const float*)d_in[5];
    const float* norm_w = (const float*)d_in[6];
    const float* w_out  = (const float*)d_in[7];
    float* out = (float*)d_out;

    void *p_qkvz, *p_ba, *p_q, *p_k, *p_v, *p_dec, *p_bet, *p_core, *p_y;
    cudaGetSymbolAddress(&p_qkvz, g_qkvz);
    cudaGetSymbolAddress(&p_ba,   g_ba);
    cudaGetSymbolAddress(&p_q,    g_q);
    cudaGetSymbolAddress(&p_k,    g_k);
    cudaGetSymbolAddress(&p_v,    g_v);
    cudaGetSymbolAddress(&p_dec,  g_decay);
    cudaGetSymbolAddress(&p_bet,  g_beta);
    cudaGetSymbolAddress(&p_core, g_core);
    cudaGetSymbolAddress(&p_y,    g_y);

    float* qkvz = (float*)p_qkvz;
    float* ba   = (float*)p_ba;
    float* q    = (float*)p_q;
    float* k    = (float*)p_k;
    float* v    = (float*)p_v;
    float* dec  = (float*)p_dec;
    float* bet  = (float*)p_bet;
    float* core = (float*)p_core;
    float* y    = (float*)p_y;

    // 1) qkvz = hs @ w_qkvz   (4096 x 12288 x 2048)
    sgemm_kernel<<<dim3(QKVZ_COLS / 128, NTOK / 128), 256>>>(
        hs, w_qkvz, qkvz, NTOK, QKVZ_COLS, HDIM);

    // 2) ba = hs @ w_ba       (4096 x 64 x 2048)
    sgemm_kernel<<<dim3(1, NTOK / 128), 256>>>(hs, w_ba, ba, NTOK, 64, HDIM);

    // 3) conv + silu + l2norm + gates
    conv_kernel<<<NTOK, 512>>>(qkvz, ba, conv_w, A_log, dt_b,
                               q, k, v, dec, bet);

    // 4) delta-rule scan
    scan_kernel<<<BATCH * HV * 2, 256>>>(q, k, v, dec, bet, core);

    // 5) gated RMSNorm
    post_kernel<<<NTOK, 1024>>>(core, qkvz, norm_w, y);

    // 6) out = y @ w_out      (4096 x 2048 x 4096)
    sgemm_kernel<<<dim3(HDIM / 128, NTOK / 128), 256>>>(
        y, w_out, out, NTOK, HDIM, VAL_DIM);
}